// round 14
// baseline (speedup 1.0000x reference)
#include <cuda_runtime.h>

#define N_ROWS 8000
#define D 9
#define N4 2000            // N_ROWS / 4 (float4 columns)
#define OUT_TPB 256
#define ROWS_PER_BLK 16
#define CHUNK 64           // rows per prologue block
#define NB1 125            // 125 * 64 = 8000
#define K1_TPB 64

// Scratch (device globals — no allocation allowed)
__device__ float d_w1bar[N_ROWS];
__device__ float d_g[N_ROWS];
__device__ float d_h[N_ROWS];

// ---------------------------------------------------------------------------
// K1 (single prologue kernel, fully sync-free):
// Block b's exclusive prefix over rows [0, 64b) computed ALGEBRAICALLY:
//   delta_row = sum_d [ ((x-c1)/a1)^2 - ((x-c2)/a2)^2 ]
//             = sum_d [ A*x^2 + B*x ] + K          (quadratic, rowless!)
//   prefix(b) = A*Sum(x^2) + B*Sum(x) + 64b*K  over flat x[0 : 576b)
// -> contiguous float4 reduction, L2-hot, no cross-block dependency.
// Then own-chunk rowstats + 64-row inclusive shfl-cumsum + sigmoid:
//   w1bar[r] = 1/(1+exp(prefix + v[r])),  g[r] = f1-f2,  h[r] = f2.
// ---------------------------------------------------------------------------
__global__ void __launch_bounds__(K1_TPB)
k_proall(const float* __restrict__ x,
         const float* __restrict__ a1, const float* __restrict__ c1,
         const float* __restrict__ a2, const float* __restrict__ c2,
         const float* __restrict__ wf1, const float* __restrict__ bf1,
         const float* __restrict__ wf2, const float* __restrict__ bf2)
{
    __shared__ float s_red[4];       // {sx_w0, sx_w1, sxx_w0, sxx_w1}
    __shared__ float s_w0tot;

    const int t = threadIdx.x;
    const int b = blockIdx.x;
    const unsigned lane = t & 31;
    const int w = t >> 5;

    const float C1 = __ldg(c1), C2 = __ldg(c2);
    const float inv1 = 1.0f / __ldg(a1);
    const float inv2 = 1.0f / __ldg(a2);
    const float i1sq = inv1 * inv1, i2sq = inv2 * inv2;
    const float Aq = i1sq - i2sq;
    const float Bq = -2.0f * (C1 * i1sq - C2 * i2sq);
    const float Kq = (float)D * (C1 * C1 * i1sq - C2 * C2 * i2sq);

    // ---- exclusive prefix via flat quadratic reduction over x[0 : 576b) ----
    float sx = 0.f, sxx = 0.f;
    {
        const int n4 = 144 * b;                 // float4 count (576b floats)
        const float4* px = reinterpret_cast<const float4*>(x);
        for (int i = t; i < n4; i += K1_TPB) {
            float4 v = __ldg(&px[i]);
            sx  += (v.x + v.y) + (v.z + v.w);
            sxx += fmaf(v.x, v.x, v.y * v.y) + fmaf(v.z, v.z, v.w * v.w);
        }
    }
#pragma unroll
    for (int o = 16; o > 0; o >>= 1) {
        sx  += __shfl_down_sync(0xffffffff, sx,  o);
        sxx += __shfl_down_sync(0xffffffff, sxx, o);
    }
    if (lane == 0) { s_red[w] = sx; s_red[2 + w] = sxx; }
    __syncthreads();
    const float prefix = fmaf(Aq, s_red[2] + s_red[3],
                         fmaf(Bq, s_red[0] + s_red[1],
                              (float)(CHUNK * b) * Kq));

    // ---- own-chunk rowstats: one row per thread ----
    const int r = b * CHUNK + t;
    const float k1 = -C1 * inv1;
    const float k2 = -C2 * inv2;
    float s1 = 0.f, s2 = 0.f;
    float f1 = __ldg(bf1), f2 = __ldg(bf2);
#pragma unroll
    for (int d = 0; d < D; d++) {
        float xv = __ldg(&x[r * D + d]);
        float u1 = fmaf(xv, inv1, k1);
        float u2 = fmaf(xv, inv2, k2);
        s1 = fmaf(u1, u1, s1);
        s2 = fmaf(u2, u2, s2);
        f1 = fmaf(xv, __ldg(&wf1[d]), f1);
        f2 = fmaf(xv, __ldg(&wf2[d]), f2);
    }
    d_g[r] = f1 - f2;
    d_h[r] = f2;

    // within-chunk inclusive cumsum (2 warps)
    float v = s1 - s2;
#pragma unroll
    for (int o = 1; o < 32; o <<= 1) {
        float n = __shfl_up_sync(0xffffffff, v, o);
        if (lane >= o) v += n;
    }
    if (t == 31) s_w0tot = v;
    __syncthreads();
    if (w == 1) v += s_w0tot;

    // ---- apply: one exp per thread ----
    const float run = prefix + v;                // S1[r] - S2[r]
    d_w1bar[r] = 1.0f / (1.0f + __expf(run));
}

// ---------------------------------------------------------------------------
// K2: out[i,j] = h[i] + g[i]*w1bar[j] — the proven 37.4 us configuration:
// 16 rows/block, 4000 blocks, 26 regs, no smem, streaming float4 stores.
// ---------------------------------------------------------------------------
__global__ void k_outer(float* __restrict__ out)
{
    cudaGridDependencySynchronize();

    int j4 = blockIdx.x * OUT_TPB + threadIdx.x;
    if (j4 >= N4) return;

    float4 w4 = reinterpret_cast<const float4*>(d_w1bar)[j4];
    int i0 = blockIdx.y * ROWS_PER_BLK;
    float4* o4 = reinterpret_cast<float4*>(out);

#pragma unroll
    for (int k = 0; k < ROWS_PER_BLK; k++) {
        int i = i0 + k;
        float gv = d_g[i];
        float hv = d_h[i];
        float4 o;
        o.x = fmaf(gv, w4.x, hv);
        o.y = fmaf(gv, w4.y, hv);
        o.z = fmaf(gv, w4.z, hv);
        o.w = fmaf(gv, w4.w, hv);
        __stcs(&o4[(size_t)i * N4 + j4], o);
    }
}

// ---------------------------------------------------------------------------
extern "C" void kernel_launch(void* const* d_in, const int* in_sizes, int n_in,
                              void* d_out, int out_size)
{
    const float* x   = (const float*)d_in[0];
    const float* a1  = (const float*)d_in[1];
    const float* c1  = (const float*)d_in[2];
    const float* a2  = (const float*)d_in[3];
    const float* c2  = (const float*)d_in[4];
    const float* wf1 = (const float*)d_in[5];
    const float* bf1 = (const float*)d_in[6];
    const float* wf2 = (const float*)d_in[7];
    const float* bf2 = (const float*)d_in[8];
    float* out = (float*)d_out;

    k_proall<<<NB1, K1_TPB>>>(x, a1, c1, a2, c2, wf1, bf1, wf2, bf2);

    // k_outer, PDL-chained behind k_proall (overlaps launch with prologue tail)
    cudaLaunchAttribute attr[1];
    attr[0].id = cudaLaunchAttributeProgrammaticStreamSerialization;
    attr[0].val.programmaticStreamSerializationAllowed = 1;

    cudaLaunchConfig_t cfgO = {};
    cfgO.gridDim  = dim3((N4 + OUT_TPB - 1) / OUT_TPB, N_ROWS / ROWS_PER_BLK);  // (8, 500)
    cfgO.blockDim = dim3(OUT_TPB, 1, 1);
    cfgO.attrs = attr;
    cfgO.numAttrs = 1;
    cudaLaunchKernelEx(&cfgO, k_outer, out);
}

// round 15
// speedup vs baseline: 1.2249x; 1.2249x over previous
#include <cuda_runtime.h>

#define N_ROWS 8000
#define D 9
#define N4 2000            // N_ROWS / 4 (float4 columns)
#define OUT_TPB 256
#define ROWS_PER_BLK 16
#define CHUNK 64           // rows per prologue block
#define NB1 125            // 125 * 64 = 8000
#define K1_TPB 512
#define NWARP (K1_TPB / 32)

// Scratch (device globals — no allocation allowed)
__device__ float d_w1bar[N_ROWS];
__device__ float d_g[N_ROWS];
__device__ float d_h[N_ROWS];

// ---------------------------------------------------------------------------
// K1 (single prologue kernel, fully sync-free across blocks):
// Block b's exclusive prefix over rows [0, 64b) computed ALGEBRAICALLY:
//   delta_row = sum_d [ A*x^2 + B*x ] + K       (quadratic in elements)
//   prefix(b) = A*Sum(x^2) + B*Sum(x) + 64b*K   over flat x[0 : 576b)
// Reduction: 512 threads, 4-way unrolled, 4 independent accumulator pairs
// (MLP >= 16) over L2-resident x. Then warps 0-1: own-chunk rowstats +
// 64-row inclusive shfl-cumsum + sigmoid -> w1bar, g, h.
// ---------------------------------------------------------------------------
__global__ void __launch_bounds__(K1_TPB)
k_proall(const float* __restrict__ x,
         const float* __restrict__ a1, const float* __restrict__ c1,
         const float* __restrict__ a2, const float* __restrict__ c2,
         const float* __restrict__ wf1, const float* __restrict__ bf1,
         const float* __restrict__ wf2, const float* __restrict__ bf2)
{
    __shared__ float s_sx[NWARP], s_sxx[NWARP];
    __shared__ float s_w0tot;

    const int t = threadIdx.x;
    const int b = blockIdx.x;
    const unsigned lane = t & 31;
    const int w = t >> 5;

    const float C1 = __ldg(c1), C2 = __ldg(c2);
    const float inv1 = 1.0f / __ldg(a1);
    const float inv2 = 1.0f / __ldg(a2);
    const float i1sq = inv1 * inv1, i2sq = inv2 * inv2;
    const float Aq = i1sq - i2sq;
    const float Bq = -2.0f * (C1 * i1sq - C2 * i2sq);
    const float Kq = (float)D * (C1 * C1 * i1sq - C2 * C2 * i2sq);

    // ---- flat quadratic reduction over x[0 : 576b)  (144b float4) ----
    const int n4 = 144 * b;
    const float4* px = reinterpret_cast<const float4*>(x);
    float sx0 = 0.f, sx1 = 0.f, sx2 = 0.f, sx3 = 0.f;
    float sq0 = 0.f, sq1 = 0.f, sq2 = 0.f, sq3 = 0.f;
    int i = t;
    for (; i + 3 * K1_TPB < n4; i += 4 * K1_TPB) {
        float4 v0 = __ldg(&px[i]);
        float4 v1 = __ldg(&px[i + K1_TPB]);
        float4 v2 = __ldg(&px[i + 2 * K1_TPB]);
        float4 v3 = __ldg(&px[i + 3 * K1_TPB]);
        sx0 += (v0.x + v0.y) + (v0.z + v0.w);
        sq0 += fmaf(v0.x, v0.x, v0.y * v0.y) + fmaf(v0.z, v0.z, v0.w * v0.w);
        sx1 += (v1.x + v1.y) + (v1.z + v1.w);
        sq1 += fmaf(v1.x, v1.x, v1.y * v1.y) + fmaf(v1.z, v1.z, v1.w * v1.w);
        sx2 += (v2.x + v2.y) + (v2.z + v2.w);
        sq2 += fmaf(v2.x, v2.x, v2.y * v2.y) + fmaf(v2.z, v2.z, v2.w * v2.w);
        sx3 += (v3.x + v3.y) + (v3.z + v3.w);
        sq3 += fmaf(v3.x, v3.x, v3.y * v3.y) + fmaf(v3.z, v3.z, v3.w * v3.w);
    }
    for (; i < n4; i += K1_TPB) {
        float4 v = __ldg(&px[i]);
        sx0 += (v.x + v.y) + (v.z + v.w);
        sq0 += fmaf(v.x, v.x, v.y * v.y) + fmaf(v.z, v.z, v.w * v.w);
    }
    float sx  = (sx0 + sx1) + (sx2 + sx3);
    float sxx = (sq0 + sq1) + (sq2 + sq3);
#pragma unroll
    for (int o = 16; o > 0; o >>= 1) {
        sx  += __shfl_down_sync(0xffffffff, sx,  o);
        sxx += __shfl_down_sync(0xffffffff, sxx, o);
    }
    if (lane == 0) { s_sx[w] = sx; s_sxx[w] = sxx; }
    __syncthreads();
    float tsx = 0.f, tsxx = 0.f;
#pragma unroll
    for (int k = 0; k < NWARP; k++) { tsx += s_sx[k]; tsxx += s_sxx[k]; }
    const float prefix = fmaf(Aq, tsxx, fmaf(Bq, tsx, (float)(CHUNK * b) * Kq));

    // ---- warps 0-1: own-chunk rowstats + cumsum + sigmoid ----
    float v = 0.0f;
    int r = b * CHUNK + t;
    if (t < CHUNK) {
        const float k1 = -C1 * inv1;
        const float k2 = -C2 * inv2;
        float s1 = 0.f, s2 = 0.f;
        float f1 = __ldg(bf1), f2 = __ldg(bf2);
#pragma unroll
        for (int d = 0; d < D; d++) {
            float xv = __ldg(&x[r * D + d]);
            float u1 = fmaf(xv, inv1, k1);
            float u2 = fmaf(xv, inv2, k2);
            s1 = fmaf(u1, u1, s1);
            s2 = fmaf(u2, u2, s2);
            f1 = fmaf(xv, __ldg(&wf1[d]), f1);
            f2 = fmaf(xv, __ldg(&wf2[d]), f2);
        }
        d_g[r] = f1 - f2;
        d_h[r] = f2;

        v = s1 - s2;
#pragma unroll
        for (int o = 1; o < 32; o <<= 1) {
            float n = __shfl_up_sync(0xffffffff, v, o);
            if (lane >= o) v += n;
        }
    }
    if (t == 31) s_w0tot = v;
    __syncthreads();
    if (t >= 32 && t < CHUNK) v += s_w0tot;
    if (t < CHUNK) {
        const float run = prefix + v;                // S1[r] - S2[r]
        d_w1bar[r] = 1.0f / (1.0f + __expf(run));
    }
}

// ---------------------------------------------------------------------------
// K2: out[i,j] = h[i] + g[i]*w1bar[j] — the proven 37.4 us configuration:
// 16 rows/block, 4000 blocks, 26 regs, no smem, streaming float4 stores.
// ---------------------------------------------------------------------------
__global__ void k_outer(float* __restrict__ out)
{
    cudaGridDependencySynchronize();

    int j4 = blockIdx.x * OUT_TPB + threadIdx.x;
    if (j4 >= N4) return;

    float4 w4 = reinterpret_cast<const float4*>(d_w1bar)[j4];
    int i0 = blockIdx.y * ROWS_PER_BLK;
    float4* o4 = reinterpret_cast<float4*>(out);

#pragma unroll
    for (int k = 0; k < ROWS_PER_BLK; k++) {
        int i = i0 + k;
        float gv = d_g[i];
        float hv = d_h[i];
        float4 o;
        o.x = fmaf(gv, w4.x, hv);
        o.y = fmaf(gv, w4.y, hv);
        o.z = fmaf(gv, w4.z, hv);
        o.w = fmaf(gv, w4.w, hv);
        __stcs(&o4[(size_t)i * N4 + j4], o);
    }
}

// ---------------------------------------------------------------------------
extern "C" void kernel_launch(void* const* d_in, const int* in_sizes, int n_in,
                              void* d_out, int out_size)
{
    const float* x   = (const float*)d_in[0];
    const float* a1  = (const float*)d_in[1];
    const float* c1  = (const float*)d_in[2];
    const float* a2  = (const float*)d_in[3];
    const float* c2  = (const float*)d_in[4];
    const float* wf1 = (const float*)d_in[5];
    const float* bf1 = (const float*)d_in[6];
    const float* wf2 = (const float*)d_in[7];
    const float* bf2 = (const float*)d_in[8];
    float* out = (float*)d_out;

    k_proall<<<NB1, K1_TPB>>>(x, a1, c1, a2, c2, wf1, bf1, wf2, bf2);

    // k_outer, PDL-chained behind k_proall
    cudaLaunchAttribute attr[1];
    attr[0].id = cudaLaunchAttributeProgrammaticStreamSerialization;
    attr[0].val.programmaticStreamSerializationAllowed = 1;

    cudaLaunchConfig_t cfgO = {};
    cfgO.gridDim  = dim3((N4 + OUT_TPB - 1) / OUT_TPB, N_ROWS / ROWS_PER_BLK);  // (8, 500)
    cfgO.blockDim = dim3(OUT_TPB, 1, 1);
    cfgO.attrs = attr;
    cfgO.numAttrs = 1;
    cudaLaunchKernelEx(&cfgO, k_outer, out);
}